// round 2
// baseline (speedup 1.0000x reference)
#include <cuda_runtime.h>
#include <math.h>

// ---------------- compile-time problem shape ----------------
#define TT 4096    // B*S tokens
#define DD 1024
#define HH 2048
#define OO 1024
#define EE 8
#define MAXTILES 72            // max sum over experts of ceil(cnt_e/128)  (proven <= 71)
#define BUFROWS (MAXTILES*128) // 9216

// ---------------- scratch (device globals; no allocation allowed) ----------------
__device__ float g_xn  [(size_t)TT*DD];       // LN1 output
__device__ float g_h1  [(size_t)TT*HH];       // shared expert hidden
__device__ float g_sh  [(size_t)TT*OO];       // shared expert output
__device__ float g_hid2[(size_t)BUFROWS*HH];  // expert hidden (compacted rows)
__device__ float g_eout2[(size_t)BUFROWS*OO]; // expert output (compacted rows)
__device__ int   g_tki [TT*2];
__device__ float g_tkw [TT*2];
__device__ int   g_rank[TT*2];
__device__ int   g_perm[BUFROWS];
__device__ int   g_counts[EE];
__device__ int   g_cursor[EE];
__device__ int   g_base[EE];
__device__ int   g_tile_expert[MAXTILES];
__device__ int   g_tile_rows[MAXTILES];

__device__ __forceinline__ float gelu_exact(float x) {
    return 0.5f * x * (1.0f + erff(x * 0.70710678118654752440f));
}

// block-wide 2-value sum reduce; blockDim.x == 256; sh must have >= 16 floats
__device__ __forceinline__ void block_reduce2(float& s, float& s2, float* sh) {
    #pragma unroll
    for (int o = 16; o; o >>= 1) {
        s  += __shfl_down_sync(0xffffffffu, s,  o);
        s2 += __shfl_down_sync(0xffffffffu, s2, o);
    }
    int w = threadIdx.x >> 5, l = threadIdx.x & 31;
    if (l == 0) { sh[w] = s; sh[8 + w] = s2; }
    __syncthreads();
    if (threadIdx.x == 0) {
        float a = 0.f, b = 0.f;
        #pragma unroll
        for (int i = 0; i < 8; i++) { a += sh[i]; b += sh[8 + i]; }
        sh[0] = a; sh[8] = b;
    }
    __syncthreads();
    s = sh[0]; s2 = sh[8];
}

// ---------------- LN1 (one block / token) + reset counters ----------------
__global__ void ln1_kernel(const float* __restrict__ x,
                           const float* __restrict__ g,
                           const float* __restrict__ b) {
    int t = blockIdx.x, tid = threadIdx.x;
    if (t == 0 && tid < EE) g_counts[tid] = 0;  // consumed only by later kernels
    const float* xr = x + (size_t)t * DD;
    float v[4], s = 0.f, s2 = 0.f;
    #pragma unroll
    for (int i = 0; i < 4; i++) {
        v[i] = xr[tid + i * 256];
        s += v[i]; s2 += v[i] * v[i];
    }
    __shared__ float sh[16];
    block_reduce2(s, s2, sh);
    float m   = s  * (1.0f / DD);
    float var = s2 * (1.0f / DD) - m * m;
    float inv = rsqrtf(var + 1e-5f);
    float* yr = g_xn + (size_t)t * DD;
    #pragma unroll
    for (int i = 0; i < 4; i++) {
        int d = tid + i * 256;
        yr[d] = (v[i] - m) * inv * g[d] + b[d];
    }
}

// ---------------- router: logits, softmax, top-2, counts (one block / token) ----------------
__global__ void router_kernel(const float* __restrict__ rw,
                              const float* __restrict__ rb) {
    int t = blockIdx.x, tid = threadIdx.x;
    const float* xr = g_xn + (size_t)t * DD;
    float p[EE];
    #pragma unroll
    for (int e = 0; e < EE; e++) p[e] = 0.f;
    for (int d = tid; d < DD; d += 256) {
        float xv = xr[d];
        #pragma unroll
        for (int e = 0; e < EE; e++) p[e] += xv * rw[e * DD + d];
    }
    __shared__ float s[256][EE];
    #pragma unroll
    for (int e = 0; e < EE; e++) s[tid][e] = p[e];
    __syncthreads();
    for (int o = 128; o; o >>= 1) {
        if (tid < o) {
            #pragma unroll
            for (int e = 0; e < EE; e++) s[tid][e] += s[tid + o][e];
        }
        __syncthreads();
    }
    if (tid == 0) {
        float l[EE];
        #pragma unroll
        for (int e = 0; e < EE; e++) l[e] = s[0][e] + rb[e];
        int i0 = 0;
        #pragma unroll
        for (int e = 1; e < EE; e++) if (l[e] > l[i0]) i0 = e;   // first max wins ties
        int i1 = (i0 == 0) ? 1 : 0;
        #pragma unroll
        for (int e = 0; e < EE; e++) if (e != i0 && l[e] > l[i1]) i1 = e;
        float e0 = 1.0f;                      // exp(l[i0]-l[i0])
        float e1 = expf(l[i1] - l[i0]);
        float inv = 1.0f / (e0 + e1);
        g_tki[2 * t] = i0;  g_tki[2 * t + 1] = i1;
        g_tkw[2 * t] = e0 * inv;  g_tkw[2 * t + 1] = e1 * inv;
        atomicAdd(&g_counts[i0], 1);
        atomicAdd(&g_counts[i1], 1);
    }
}

// ---------------- segment prefix (single thread; E=8 trivial) ----------------
__global__ void prefix_kernel() {
    int rowbase = 0, tile = 0;
    for (int e = 0; e < EE; e++) {
        int cnt = g_counts[e];
        g_base[e] = rowbase;
        g_cursor[e] = 0;
        int nt = (cnt + 127) >> 7;
        for (int j = 0; j < nt; j++) {
            g_tile_expert[tile] = e;
            int rem = cnt - j * 128;
            g_tile_rows[tile] = rem < 128 ? rem : 128;
            tile++;
        }
        rowbase += nt << 7;
    }
    for (; tile < MAXTILES; tile++) { g_tile_expert[tile] = -1; g_tile_rows[tile] = 0; }
}

// ---------------- placement: compact assignment list ----------------
__global__ void place_kernel() {
    int i = blockIdx.x * blockDim.x + threadIdx.x;   // 0..2T-1
    if (i >= TT * 2) return;
    int e = g_tki[i];
    int pos = g_base[e] + atomicAdd(&g_cursor[e], 1);
    g_perm[pos] = i >> 1;
    g_rank[i] = pos;
}

// ---------------- tiled SGEMM: C[M,N] = A[M,K] * B[N,K]^T + bias (opt. GELU) ----------------
// MODE 0: plain rows (shared expert).  MODE 1: A rows gathered via g_perm (expert GEMM1).
// MODE 2: A rows compact/direct, B selected per tile's expert (expert GEMM2).
template <int MODE, bool GELU>
__global__ __launch_bounds__(256)
void gemm_kernel(const float* __restrict__ A, const float* __restrict__ Bw,
                 const float* __restrict__ bias, float* __restrict__ C,
                 int N, int Kd) {
    constexpr int BM = 128, BN = 128, BK = 16;
    int tileM = blockIdx.y, tileN = blockIdx.x;
    int valid = BM;
    const float* Bp = Bw;
    const float* bp = bias;
    if (MODE != 0) {
        int e = g_tile_expert[tileM];
        if (e < 0) return;
        valid = g_tile_rows[tileM];
        if (MODE == 1) { Bp = Bw + (size_t)e * HH * DD; bp = bias + e * HH; }
        else           { Bp = Bw + (size_t)e * OO * HH; bp = bias + e * OO; }
    }
    int row0 = tileM * BM, col0 = tileN * BN;
    int tid = threadIdx.x;
    int lr = tid >> 2;            // 0..63
    int lk = (tid & 3) * 4;       // 0,4,8,12

    int i0 = lr, i1 = lr + 64;
    const float* a0p = nullptr;
    const float* a1p = nullptr;
    if (MODE == 1) {
        if (i0 < valid) a0p = A + (size_t)g_perm[row0 + i0] * Kd;
        if (i1 < valid) a1p = A + (size_t)g_perm[row0 + i1] * Kd;
    } else {
        a0p = A + (size_t)(row0 + i0) * Kd;
        a1p = A + (size_t)(row0 + i1) * Kd;
    }
    const float* b0p = Bp + (size_t)(col0 + lr) * Kd;
    const float* b1p = Bp + (size_t)(col0 + lr + 64) * Kd;

    __shared__ float As[BK][BM];
    __shared__ float Bs[BK][BN];
    float acc[8][8];
    #pragma unroll
    for (int i = 0; i < 8; i++)
        #pragma unroll
        for (int j = 0; j < 8; j++) acc[i][j] = 0.f;

    int ty = tid >> 4, tx = tid & 15;

    for (int kt = 0; kt < Kd; kt += BK) {
        float4 a0 = a0p ? *(const float4*)(a0p + kt + lk) : make_float4(0.f, 0.f, 0.f, 0.f);
        float4 a1 = a1p ? *(const float4*)(a1p + kt + lk) : make_float4(0.f, 0.f, 0.f, 0.f);
        float4 b0 = *(const float4*)(b0p + kt + lk);
        float4 b1 = *(const float4*)(b1p + kt + lk);
        As[lk + 0][i0] = a0.x; As[lk + 1][i0] = a0.y; As[lk + 2][i0] = a0.z; As[lk + 3][i0] = a0.w;
        As[lk + 0][i1] = a1.x; As[lk + 1][i1] = a1.y; As[lk + 2][i1] = a1.z; As[lk + 3][i1] = a1.w;
        Bs[lk + 0][lr]      = b0.x; Bs[lk + 1][lr]      = b0.y; Bs[lk + 2][lr]      = b0.z; Bs[lk + 3][lr]      = b0.w;
        Bs[lk + 0][lr + 64] = b1.x; Bs[lk + 1][lr + 64] = b1.y; Bs[lk + 2][lr + 64] = b1.z; Bs[lk + 3][lr + 64] = b1.w;
        __syncthreads();
        #pragma unroll
        for (int kk = 0; kk < BK; kk++) {
            float4 av0 = *(const float4*)&As[kk][ty * 8];
            float4 av1 = *(const float4*)&As[kk][ty * 8 + 4];
            float4 bv0 = *(const float4*)&Bs[kk][tx * 8];
            float4 bv1 = *(const float4*)&Bs[kk][tx * 8 + 4];
            float av[8] = {av0.x, av0.y, av0.z, av0.w, av1.x, av1.y, av1.z, av1.w};
            float bv[8] = {bv0.x, bv0.y, bv0.z, bv0.w, bv1.x, bv1.y, bv1.z, bv1.w};
            #pragma unroll
            for (int ii = 0; ii < 8; ii++)
                #pragma unroll
                for (int jj = 0; jj < 8; jj++)
                    acc[ii][jj] += av[ii] * bv[jj];
        }
        __syncthreads();
    }

    #pragma unroll
    for (int ii = 0; ii < 8; ii++) {
        int i = ty * 8 + ii;
        if (MODE != 0 && i >= valid) continue;
        size_t crow = (size_t)(row0 + i) * N + col0;
        #pragma unroll
        for (int jj = 0; jj < 8; jj++) {
            int n = tx * 8 + jj;
            float vv = acc[ii][jj] + bp[col0 + n];
            if (GELU) vv = gelu_exact(vv);
            C[crow + n] = vv;
        }
    }
}

// ---------------- combine (shared/9 + top-2 mix) + LN2, one block / token ----------------
__global__ void combine_kernel(const float* __restrict__ g2,
                               const float* __restrict__ b2,
                               float* __restrict__ out) {
    int t = blockIdx.x, tid = threadIdx.x;
    int r0 = g_rank[2 * t], r1 = g_rank[2 * t + 1];
    float w0 = g_tkw[2 * t], w1 = g_tkw[2 * t + 1];
    const float* sh = g_sh + (size_t)t * OO;
    const float* e0 = g_eout2 + (size_t)r0 * OO;
    const float* e1 = g_eout2 + (size_t)r1 * OO;
    float v[4], s = 0.f, s2 = 0.f;
    #pragma unroll
    for (int i = 0; i < 4; i++) {
        int o = tid + i * 256;
        v[i] = sh[o] * (1.0f / 9.0f) + w0 * e0[o] + w1 * e1[o];
        s += v[i]; s2 += v[i] * v[i];
    }
    __shared__ float shm[16];
    block_reduce2(s, s2, shm);
    float m   = s  * (1.0f / OO);
    float var = s2 * (1.0f / OO) - m * m;
    float inv = rsqrtf(var + 1e-5f);
    float* orow = out + (size_t)t * OO;
    #pragma unroll
    for (int i = 0; i < 4; i++) {
        int o = tid + i * 256;
        orow[o] = (v[i] - m) * inv * g2[o] + b2[o];
    }
}

// ---------------- launch ----------------
extern "C" void kernel_launch(void* const* d_in, const int* in_sizes, int n_in,
                              void* d_out, int out_size) {
    const float* x        = (const float*)d_in[0];
    const float* ln1_g    = (const float*)d_in[1];
    const float* ln1_b    = (const float*)d_in[2];
    const float* router_w = (const float*)d_in[3];
    const float* router_b = (const float*)d_in[4];
    const float* sh_w1    = (const float*)d_in[5];
    const float* sh_b1    = (const float*)d_in[6];
    const float* sh_w2    = (const float*)d_in[7];
    const float* sh_b2    = (const float*)d_in[8];
    const float* e_w1     = (const float*)d_in[9];
    const float* e_b1     = (const float*)d_in[10];
    const float* e_w2     = (const float*)d_in[11];
    const float* e_b2     = (const float*)d_in[12];
    const float* ln2_g    = (const float*)d_in[13];
    const float* ln2_b    = (const float*)d_in[14];
    float* out = (float*)d_out;

    float *p_xn, *p_h1, *p_sh, *p_hid2, *p_eout2;
    cudaGetSymbolAddress((void**)&p_xn,    g_xn);
    cudaGetSymbolAddress((void**)&p_h1,    g_h1);
    cudaGetSymbolAddress((void**)&p_sh,    g_sh);
    cudaGetSymbolAddress((void**)&p_hid2,  g_hid2);
    cudaGetSymbolAddress((void**)&p_eout2, g_eout2);

    // 1) LN1 (+ counter reset)
    ln1_kernel<<<TT, 256>>>(x, ln1_g, ln1_b);
    // 2) router: top-2 + counts
    router_kernel<<<TT, 256>>>(router_w, router_b);
    // 3) segment layout
    prefix_kernel<<<1, 1>>>();
    // 4) compact placement
    place_kernel<<<(TT * 2) / 256, 256>>>();
    // 5) shared expert GEMM1 (GELU) : [T,H] = xn @ sh_w1^T
    gemm_kernel<0, true ><<<dim3(HH / 128, TT / 128), 256>>>(p_xn, sh_w1, sh_b1, p_h1, HH, DD);
    // 6) shared expert GEMM2        : [T,O] = h1 @ sh_w2^T
    gemm_kernel<0, false><<<dim3(OO / 128, TT / 128), 256>>>(p_h1, sh_w2, sh_b2, p_sh, OO, HH);
    // 7) expert GEMM1 (gathered rows, GELU) : hid2 = xn[perm] @ e_w1[e]^T
    gemm_kernel<1, true ><<<dim3(HH / 128, MAXTILES), 256>>>(p_xn, e_w1, e_b1, p_hid2, HH, DD);
    // 8) expert GEMM2 (compact rows)        : eout2 = hid2 @ e_w2[e]^T
    gemm_kernel<2, false><<<dim3(OO / 128, MAXTILES), 256>>>(p_hid2, e_w2, e_b2, p_eout2, OO, HH);
    // 9) combine + LN2
    combine_kernel<<<TT, 256>>>(ln2_g, ln2_b, out);
}